// round 7
// baseline (speedup 1.0000x reference)
#include <cuda_runtime.h>
#include <cuda_bf16.h>
#include <cuda_fp16.h>
#include <cstdint>
#include <math.h>

// ============================================================================
// MLP: out[e] = gelu_tanh(x[e] @ w1[e]) @ w2[e]
//   E=8, T=2048, H=1024, F=4096, fp32 in/out.
// Both GEMMs: 2-product fp16 split (A fp16 single, B fp16 hi/lo), fp32 acc.
// warp mma.sync m16n8k16; 8 warps, warp tile 64x64, CTA 128x256:
//   per kk-step SM-wide: 384 LDS wavefronts vs 512 MMA cycles -> tensor-bound
//   (R5 was 256:256 balanced, R6 was 384:256 LDS-bound).
// cp.async 2-stage pipeline (80KB/stage), SW128 swizzle, ldmatrix fragments.
// Error (calibrated): 2.08e-4 per fp16 rounding event x2 -> ~3e-4 (thr 1e-3).
// ============================================================================

static constexpr int E_ = 8, T_ = 2048, H_ = 1024, F_ = 4096;

// -------- static device scratch --------
__device__ __half g_x16[(size_t)E_ * T_ * H_];        // x fp16
__device__ __half g_w1h[(size_t)E_ * F_ * H_];        // w1^T: [E,F,H] fp16 hi
__device__ __half g_w1l[(size_t)E_ * F_ * H_];
__device__ __half g_w2h[(size_t)E_ * H_ * F_];        // w2^T: [E,H,F] fp16 hi
__device__ __half g_w2l[(size_t)E_ * H_ * F_];
__device__ __half g_h16[(size_t)E_ * T_ * F_];        // gelu(x@w1) fp16

// -------- helpers --------
__device__ __forceinline__ uint32_t smem_u32(const void* p) {
    return (uint32_t)__cvta_generic_to_shared(p);
}
__device__ __forceinline__ void cp16(uint32_t s, const void* g) {
    asm volatile("cp.async.cg.shared.global [%0], [%1], 16;\n"
                 :: "r"(s), "l"(__cvta_generic_to_global(g)));
}
__device__ __forceinline__ void cp_commit() {
    asm volatile("cp.async.commit_group;\n" ::: "memory");
}
template <int N> __device__ __forceinline__ void cp_wait() {
    asm volatile("cp.async.wait_group %0;\n" :: "n"(N) : "memory");
}
#define SWZ(x) ((x) ^ (((x) >> 3) & 0x70))

#define LDSM_X4(r0, r1, r2, r3, a)                                          \
    asm volatile("ldmatrix.sync.aligned.m8n8.x4.shared.b16 {%0,%1,%2,%3}, [%4];" \
                 : "=r"(r0), "=r"(r1), "=r"(r2), "=r"(r3) : "r"(a))

__device__ __forceinline__ void mma16816(float* c, const uint32_t* a, const uint32_t* b) {
    asm volatile(
        "mma.sync.aligned.m16n8k16.row.col.f32.f16.f16.f32 "
        "{%0,%1,%2,%3}, {%4,%5,%6,%7}, {%8,%9}, {%0,%1,%2,%3};\n"
        : "+f"(c[0]), "+f"(c[1]), "+f"(c[2]), "+f"(c[3])
        : "r"(a[0]), "r"(a[1]), "r"(a[2]), "r"(a[3]), "r"(b[0]), "r"(b[1]));
}

__device__ __forceinline__ float gelu_tanh_f(float x) {
    float inner = 0.7978845608028654f * (x + 0.044715f * x * x * x);
    return 0.5f * x * (1.0f + tanhf(inner));
}

// -------- pre-pass: fp32 -> fp16 convert (x) --------
__global__ void conv16_k(const float* __restrict__ in, __half* __restrict__ o, size_t n4) {
    size_t i = (size_t)blockIdx.x * blockDim.x + threadIdx.x;
    if (i >= n4) return;
    float4 v = ((const float4*)in)[i];
    __half2 a = __floats2half2_rn(v.x, v.y);
    __half2 b = __floats2half2_rn(v.z, v.w);
    ((uint2*)o)[i] = make_uint2(*(uint32_t*)&a, *(uint32_t*)&b);
}

// -------- pre-pass: transpose [E,R,C] -> [E,C,R] + fp16 hi/lo split --------
__global__ void tsplit16(const float* __restrict__ in, __half* __restrict__ hi,
                         __half* __restrict__ lo, int R, int C) {
    __shared__ float t[32][33];  // t[r_local][c_local]
    int e = blockIdx.z;
    const float* ip = in + (size_t)e * R * C;
    size_t ob = (size_t)e * R * C;
    int c0 = blockIdx.x * 32, r0 = blockIdx.y * 32;
    int tx = threadIdx.x, ty = threadIdx.y;
    for (int j = ty; j < 32; j += 8)
        t[j][tx] = ip[(size_t)(r0 + j) * C + c0 + tx];
    __syncthreads();
#pragma unroll
    for (int it = 0; it < 2; it++) {
        int cc = it * 16 + ty * 2 + (tx >> 4);   // c_local
        int rr = (tx & 15) * 2;                  // r_local (pair)
        float v0 = t[rr][cc], v1 = t[rr + 1][cc];
        __half h0 = __float2half_rn(v0), h1 = __float2half_rn(v1);
        __half l0 = __float2half_rn(v0 - __half2float(h0));
        __half l1 = __float2half_rn(v1 - __half2float(h1));
        size_t o = ob + (size_t)(c0 + cc) * R + r0 + rr;
        __half2 hp = __halves2half2(h0, h1), lp = __halves2half2(l0, l1);
        *(uint32_t*)(hi + o) = *(uint32_t*)&hp;
        *(uint32_t*)(lo + o) = *(uint32_t*)&lp;
    }
}

// -------- warp-mma GEMM: C[M,N] = A[M,K] @ B[N,K]^T, 2 fp16 products ------
#define CTA_M 128
#define CTA_N 256
#define CTA_K 64
#define NTHREADS 256
#define A_BYTES (128 * 128)         // 128 rows x 128B = 16 KB
#define B_BYTES (256 * 128)         // 256 rows x 128B = 32 KB
#define STAGE_BYTES (A_BYTES + 2 * B_BYTES)  // 80 KB
#define SMEM_TOTAL (2 * STAGE_BYTES)          // 160 KB

template <bool FUSE_GELU>
__global__ __launch_bounds__(NTHREADS, 1)
void gemm_wm(const __half* __restrict__ A0, const __half* __restrict__ B0,
             const __half* __restrict__ B1, float* __restrict__ Cf,
             __half* __restrict__ Ch, int M, int N, int K) {
    extern __shared__ __align__(1024) char smem[];
    uint32_t sb = smem_u32(smem);
    const int tid = threadIdx.x, warp = tid >> 5, lid = tid & 31;
    const int e = blockIdx.z;
    const int m0 = blockIdx.y * CTA_M, n0 = blockIdx.x * CTA_N;
    const int wm = (warp >> 2) * 64;    // 2 warp rows x 64
    const int wn = (warp & 3) * 64;     // 4 warp cols x 64
    const int g = lid >> 2, q = lid & 3;

    size_t eA = (size_t)e * M * K, eB = (size_t)e * N * K;
    const __half* gA = A0 + eA + (size_t)m0 * K;
    const __half* gBh = B0 + eB + (size_t)n0 * K;
    const __half* gBl = B1 + eB + (size_t)n0 * K;

    float acc[4][8][4];
#pragma unroll
    for (int mi = 0; mi < 4; mi++)
#pragma unroll
        for (int ni = 0; ni < 8; ni++)
#pragma unroll
            for (int k2 = 0; k2 < 4; k2++) acc[mi][ni][k2] = 0.0f;

    auto load_stage = [&](int kt, int s) {
        uint32_t st = sb + s * STAGE_BYTES;
        int k0 = kt * CTA_K;
        // A: 128 rows x 8 chunks = 1024
#pragma unroll
        for (int i = 0; i < 4; i++) {
            int c = i * NTHREADS + tid;
            int row = c >> 3, h = c & 7;
            uint32_t rel = (uint32_t)(row * 128 + h * 16);
            cp16(st + SWZ(rel), gA + (size_t)row * K + k0 + h * 8);
        }
        // Bh/Bl: 256 rows x 8 chunks = 2048 each
#pragma unroll
        for (int i = 0; i < 8; i++) {
            int c = i * NTHREADS + tid;
            int row = c >> 3, h = c & 7;
            uint32_t rel = (uint32_t)(row * 128 + h * 16);
            uint32_t sw = SWZ(rel);
            size_t go = (size_t)row * K + k0 + h * 8;
            cp16(st + A_BYTES + sw, gBh + go);
            cp16(st + A_BYTES + B_BYTES + sw, gBl + go);
        }
    };

    auto compute = [&](int s) {
        uint32_t st = sb + s * STAGE_BYTES;
        uint32_t aA = st;
        uint32_t bH = st + A_BYTES, bL = st + A_BYTES + B_BYTES;
#pragma unroll
        for (int kk = 0; kk < CTA_K; kk += 16) {
            uint32_t av[4][4], bb[8][2];
            // A fragments: 4 x4
            {
                int arow = wm + (lid & 15);
                uint32_t acol = (uint32_t)(kk * 2 + (lid >> 4) * 16);
#pragma unroll
                for (int mi = 0; mi < 4; mi++) {
                    uint32_t rel = (uint32_t)((arow + mi * 16) * 128) + acol;
                    uint32_t ad = SWZ(rel);
                    LDSM_X4(av[mi][0], av[mi][1], av[mi][2], av[mi][3], aA + ad);
                }
            }
            int brow = wn + ((lid >> 4) & 1) * 8 + (lid & 7);
            uint32_t bcol = (uint32_t)(kk * 2 + ((lid >> 3) & 1) * 16);
            // Bh fragments + 32 MMAs
#pragma unroll
            for (int nf = 0; nf < 4; nf++) {
                uint32_t rel = (uint32_t)((brow + nf * 16) * 128) + bcol;
                uint32_t ad = SWZ(rel);
                LDSM_X4(bb[nf * 2][0], bb[nf * 2][1], bb[nf * 2 + 1][0], bb[nf * 2 + 1][1],
                        bH + ad);
            }
#pragma unroll
            for (int mi = 0; mi < 4; mi++)
#pragma unroll
                for (int ni = 0; ni < 8; ni++) mma16816(acc[mi][ni], av[mi], bb[ni]);
            // Bl fragments (reuse regs) + 32 MMAs
#pragma unroll
            for (int nf = 0; nf < 4; nf++) {
                uint32_t rel = (uint32_t)((brow + nf * 16) * 128) + bcol;
                uint32_t ad = SWZ(rel);
                LDSM_X4(bb[nf * 2][0], bb[nf * 2][1], bb[nf * 2 + 1][0], bb[nf * 2 + 1][1],
                        bL + ad);
            }
#pragma unroll
            for (int mi = 0; mi < 4; mi++)
#pragma unroll
                for (int ni = 0; ni < 8; ni++) mma16816(acc[mi][ni], av[mi], bb[ni]);
        }
    };

    const int NK = K / CTA_K;
    load_stage(0, 0);
    cp_commit();
    load_stage(1, 1);
    cp_commit();

    for (int kt = 0; kt < NK; kt++) {
        int s = kt & 1;
        cp_wait<1>();           // stage s loads complete
        __syncthreads();
        compute(s);
        __syncthreads();        // stage s consumed by all warps
        if (kt + 2 < NK) load_stage(kt + 2, s);
        cp_commit();            // commit every iter (possibly empty) to keep count
    }

    // ---- epilogue ----
#pragma unroll
    for (int mi = 0; mi < 4; mi++) {
#pragma unroll
        for (int ni = 0; ni < 8; ni++) {
            int r = m0 + wm + mi * 16 + g;
            int col = n0 + wn + ni * 8 + q * 2;
            size_t o0 = ((size_t)e * M + r) * N + col;
            size_t o1 = o0 + (size_t)8 * N;
            float v0 = acc[mi][ni][0], v1 = acc[mi][ni][1];
            float v2 = acc[mi][ni][2], v3 = acc[mi][ni][3];
            if (FUSE_GELU) {
                v0 = gelu_tanh_f(v0); v1 = gelu_tanh_f(v1);
                v2 = gelu_tanh_f(v2); v3 = gelu_tanh_f(v3);
                __half2 p0 = __floats2half2_rn(v0, v1);
                __half2 p1 = __floats2half2_rn(v2, v3);
                *(__half2*)(Ch + o0) = p0;
                *(__half2*)(Ch + o1) = p1;
            } else {
                *(float2*)(Cf + o0) = make_float2(v0, v1);
                *(float2*)(Cf + o1) = make_float2(v2, v3);
            }
        }
    }
}

// -------- host launch --------
extern "C" void kernel_launch(void* const* d_in, const int* in_sizes, int n_in,
                              void* d_out, int out_size) {
    const float* x = (const float*)d_in[0];
    const float* w1 = (const float*)d_in[1];
    const float* w2 = (const float*)d_in[2];
    float* out = (float*)d_out;

    __half *x16, *w1h, *w1l, *w2h, *w2l, *h16;
    cudaGetSymbolAddress((void**)&x16, g_x16);
    cudaGetSymbolAddress((void**)&w1h, g_w1h);
    cudaGetSymbolAddress((void**)&w1l, g_w1l);
    cudaGetSymbolAddress((void**)&w2h, g_w2h);
    cudaGetSymbolAddress((void**)&w2l, g_w2l);
    cudaGetSymbolAddress((void**)&h16, g_h16);

    cudaFuncSetAttribute(gemm_wm<true>, cudaFuncAttributeMaxDynamicSharedMemorySize, SMEM_TOTAL);
    cudaFuncSetAttribute(gemm_wm<false>, cudaFuncAttributeMaxDynamicSharedMemorySize, SMEM_TOTAL);

    // pre-pass
    size_t nx4 = (size_t)E_ * T_ * H_ / 4;
    conv16_k<<<(unsigned)((nx4 + 255) / 256), 256>>>(x, x16, nx4);
    tsplit16<<<dim3(F_ / 32, H_ / 32, E_), dim3(32, 8)>>>(w1, w1h, w1l, H_, F_);
    tsplit16<<<dim3(H_ / 32, F_ / 32, E_), dim3(32, 8)>>>(w2, w2h, w2l, F_, H_);

    // GEMM1 + GELU: A=x fp16 [T,H], B=w1^T fp16 hi/lo [F,H] -> h fp16 [T,F]
    gemm_wm<true><<<dim3(F_ / CTA_N, T_ / CTA_M, E_), NTHREADS, SMEM_TOTAL>>>(
        x16, w1h, w1l, nullptr, h16, T_, F_, H_);
    // GEMM2: A=h fp16 [T,F], B=w2^T fp16 hi/lo [H,F] -> out fp32 [T,H]
    gemm_wm<false><<<dim3(H_ / CTA_N, T_ / CTA_M, E_), NTHREADS, SMEM_TOTAL>>>(
        h16, w2h, w2l, out, nullptr, T_, H_, F_);
}

// round 8
// speedup vs baseline: 1.0784x; 1.0784x over previous
#include <cuda_runtime.h>
#include <cuda_bf16.h>
#include <cuda_fp16.h>
#include <cstdint>
#include <math.h>

// ============================================================================
// MLP: out[e] = gelu_tanh(x[e] @ w1[e]) @ w2[e]
//   E=8, T=2048, H=1024, F=4096, fp32 in/out.
// Both GEMMs: 2-product fp16 split (A fp16 single, B fp16 hi/lo), fp32 acc.
// warp mma.sync m16n8k16; 8 warps, warp tile 64x32, CTA 128x128.
// KEY CHANGE (R8): 2 stages x 48KB smem + __launch_bounds__(256,2)
//   -> 2 CTAs resident per SM; cross-CTA work covers barrier/cp.async
//   refill stalls that capped tensor% at ~68 with 1 CTA/SM.
// Error (calibrated): 2.08e-4 per fp16 rounding event x2 -> ~3e-4 (thr 1e-3).
// ============================================================================

static constexpr int E_ = 8, T_ = 2048, H_ = 1024, F_ = 4096;

// -------- static device scratch --------
__device__ __half g_x16[(size_t)E_ * T_ * H_];        // x fp16
__device__ __half g_w1h[(size_t)E_ * F_ * H_];        // w1^T: [E,F,H] fp16 hi
__device__ __half g_w1l[(size_t)E_ * F_ * H_];
__device__ __half g_w2h[(size_t)E_ * H_ * F_];        // w2^T: [E,H,F] fp16 hi
__device__ __half g_w2l[(size_t)E_ * H_ * F_];
__device__ __half g_h16[(size_t)E_ * T_ * F_];        // gelu(x@w1) fp16

// -------- helpers --------
__device__ __forceinline__ uint32_t smem_u32(const void* p) {
    return (uint32_t)__cvta_generic_to_shared(p);
}
__device__ __forceinline__ void cp16(uint32_t s, const void* g) {
    asm volatile("cp.async.cg.shared.global [%0], [%1], 16;\n"
                 :: "r"(s), "l"(__cvta_generic_to_global(g)));
}
__device__ __forceinline__ void cp_commit() {
    asm volatile("cp.async.commit_group;\n" ::: "memory");
}
template <int N> __device__ __forceinline__ void cp_wait() {
    asm volatile("cp.async.wait_group %0;\n" :: "n"(N) : "memory");
}
#define SWZ(x) ((x) ^ (((x) >> 3) & 0x70))

#define LDSM_X4(r0, r1, r2, r3, a)                                          \
    asm volatile("ldmatrix.sync.aligned.m8n8.x4.shared.b16 {%0,%1,%2,%3}, [%4];" \
                 : "=r"(r0), "=r"(r1), "=r"(r2), "=r"(r3) : "r"(a))

__device__ __forceinline__ void mma16816(float* c, const uint32_t* a, const uint32_t* b) {
    asm volatile(
        "mma.sync.aligned.m16n8k16.row.col.f32.f16.f16.f32 "
        "{%0,%1,%2,%3}, {%4,%5,%6,%7}, {%8,%9}, {%0,%1,%2,%3};\n"
        : "+f"(c[0]), "+f"(c[1]), "+f"(c[2]), "+f"(c[3])
        : "r"(a[0]), "r"(a[1]), "r"(a[2]), "r"(a[3]), "r"(b[0]), "r"(b[1]));
}

__device__ __forceinline__ float gelu_tanh_f(float x) {
    float inner = 0.7978845608028654f * (x + 0.044715f * x * x * x);
    return 0.5f * x * (1.0f + tanhf(inner));
}

// -------- pre-pass: fp32 -> fp16 convert (x) --------
__global__ void conv16_k(const float* __restrict__ in, __half* __restrict__ o, size_t n4) {
    size_t i = (size_t)blockIdx.x * blockDim.x + threadIdx.x;
    if (i >= n4) return;
    float4 v = ((const float4*)in)[i];
    __half2 a = __floats2half2_rn(v.x, v.y);
    __half2 b = __floats2half2_rn(v.z, v.w);
    ((uint2*)o)[i] = make_uint2(*(uint32_t*)&a, *(uint32_t*)&b);
}

// -------- pre-pass: transpose [E,R,C] -> [E,C,R] + fp16 hi/lo split --------
__global__ void tsplit16(const float* __restrict__ in, __half* __restrict__ hi,
                         __half* __restrict__ lo, int R, int C) {
    __shared__ float t[32][33];  // t[r_local][c_local]
    int e = blockIdx.z;
    const float* ip = in + (size_t)e * R * C;
    size_t ob = (size_t)e * R * C;
    int c0 = blockIdx.x * 32, r0 = blockIdx.y * 32;
    int tx = threadIdx.x, ty = threadIdx.y;
    for (int j = ty; j < 32; j += 8)
        t[j][tx] = ip[(size_t)(r0 + j) * C + c0 + tx];
    __syncthreads();
#pragma unroll
    for (int it = 0; it < 2; it++) {
        int cc = it * 16 + ty * 2 + (tx >> 4);   // c_local
        int rr = (tx & 15) * 2;                  // r_local (pair)
        float v0 = t[rr][cc], v1 = t[rr + 1][cc];
        __half h0 = __float2half_rn(v0), h1 = __float2half_rn(v1);
        __half l0 = __float2half_rn(v0 - __half2float(h0));
        __half l1 = __float2half_rn(v1 - __half2float(h1));
        size_t o = ob + (size_t)(c0 + cc) * R + r0 + rr;
        __half2 hp = __halves2half2(h0, h1), lp = __halves2half2(l0, l1);
        *(uint32_t*)(hi + o) = *(uint32_t*)&hp;
        *(uint32_t*)(lo + o) = *(uint32_t*)&lp;
    }
}

// -------- warp-mma GEMM: C[M,N] = A[M,K] @ B[N,K]^T, 2 fp16 products ------
#define CTA_M 128
#define CTA_N 128
#define CTA_K 64
#define NTHREADS 256
#define ARR_BYTES (128 * 128)       // 128 rows x 128B (64 halves) = 16 KB
#define STAGE_BYTES (3 * ARR_BYTES) // A, Bh, Bl = 48 KB
#define SMEM_TOTAL (2 * STAGE_BYTES)  // 96 KB -> 2 CTAs/SM

template <bool FUSE_GELU>
__global__ __launch_bounds__(NTHREADS, 2)
void gemm_wm(const __half* __restrict__ A0, const __half* __restrict__ B0,
             const __half* __restrict__ B1, float* __restrict__ Cf,
             __half* __restrict__ Ch, int M, int N, int K) {
    extern __shared__ __align__(1024) char smem[];
    uint32_t sb = smem_u32(smem);
    const int tid = threadIdx.x, warp = tid >> 5, lid = tid & 31;
    const int e = blockIdx.z;
    const int m0 = blockIdx.y * CTA_M, n0 = blockIdx.x * CTA_N;
    const int wm = (warp >> 2) * 64;    // 2 warp rows x 64
    const int wn = (warp & 3) * 32;     // 4 warp cols x 32
    const int g = lid >> 2, q = lid & 3;

    size_t eA = (size_t)e * M * K, eB = (size_t)e * N * K;
    const __half* gA = A0 + eA + (size_t)m0 * K;
    const __half* gBh = B0 + eB + (size_t)n0 * K;
    const __half* gBl = B1 + eB + (size_t)n0 * K;

    float acc[4][4][4];
#pragma unroll
    for (int mi = 0; mi < 4; mi++)
#pragma unroll
        for (int ni = 0; ni < 4; ni++)
#pragma unroll
            for (int k2 = 0; k2 < 4; k2++) acc[mi][ni][k2] = 0.0f;

    auto load_stage = [&](int kt, int s) {
        uint32_t st = sb + s * STAGE_BYTES;
        int k0 = kt * CTA_K;
#pragma unroll
        for (int i = 0; i < 4; i++) {
            int c = i * NTHREADS + tid;
            int row = c >> 3, h = c & 7;
            uint32_t rel = (uint32_t)(row * 128 + h * 16);
            uint32_t sw = SWZ(rel);
            size_t go = (size_t)row * K + k0 + h * 8;
            cp16(st + sw, gA + go);
            cp16(st + ARR_BYTES + sw, gBh + go);
            cp16(st + 2 * ARR_BYTES + sw, gBl + go);
        }
    };

    auto compute = [&](int s) {
        uint32_t st = sb + s * STAGE_BYTES;
        uint32_t aA = st;
        uint32_t bH = st + ARR_BYTES, bL = st + 2 * ARR_BYTES;
#pragma unroll
        for (int kk = 0; kk < CTA_K; kk += 16) {
            uint32_t av[4][4], bb[4][2];
            // A fragments: 4 x LDSM.x4 (64 rows x 16 k)
            {
                int arow = wm + (lid & 15);
                uint32_t acol = (uint32_t)(kk * 2 + (lid >> 4) * 16);
#pragma unroll
                for (int mi = 0; mi < 4; mi++) {
                    uint32_t rel = (uint32_t)((arow + mi * 16) * 128) + acol;
                    uint32_t ad = SWZ(rel);
                    LDSM_X4(av[mi][0], av[mi][1], av[mi][2], av[mi][3], aA + ad);
                }
            }
            int brow = wn + ((lid >> 4) & 1) * 8 + (lid & 7);
            uint32_t bcol = (uint32_t)(kk * 2 + ((lid >> 3) & 1) * 16);
            // Bh fragments (2 x LDSM.x4) + 16 MMAs
#pragma unroll
            for (int nf = 0; nf < 2; nf++) {
                uint32_t rel = (uint32_t)((brow + nf * 16) * 128) + bcol;
                uint32_t ad = SWZ(rel);
                LDSM_X4(bb[nf * 2][0], bb[nf * 2][1], bb[nf * 2 + 1][0], bb[nf * 2 + 1][1],
                        bH + ad);
            }
#pragma unroll
            for (int mi = 0; mi < 4; mi++)
#pragma unroll
                for (int ni = 0; ni < 4; ni++) mma16816(acc[mi][ni], av[mi], bb[ni]);
            // Bl fragments (reuse regs) + 16 MMAs
#pragma unroll
            for (int nf = 0; nf < 2; nf++) {
                uint32_t rel = (uint32_t)((brow + nf * 16) * 128) + bcol;
                uint32_t ad = SWZ(rel);
                LDSM_X4(bb[nf * 2][0], bb[nf * 2][1], bb[nf * 2 + 1][0], bb[nf * 2 + 1][1],
                        bL + ad);
            }
#pragma unroll
            for (int mi = 0; mi < 4; mi++)
#pragma unroll
                for (int ni = 0; ni < 4; ni++) mma16816(acc[mi][ni], av[mi], bb[ni]);
        }
    };

    const int NK = K / CTA_K;
    load_stage(0, 0);
    cp_commit();
    load_stage(1, 1);
    cp_commit();

    for (int kt = 0; kt < NK; kt++) {
        int s = kt & 1;
        cp_wait<1>();           // stage s loads complete
        __syncthreads();
        compute(s);
        __syncthreads();        // stage s consumed by all warps
        if (kt + 2 < NK) load_stage(kt + 2, s);
        cp_commit();            // commit every iter (possibly empty) to keep count
    }

    // ---- epilogue ----
#pragma unroll
    for (int mi = 0; mi < 4; mi++) {
#pragma unroll
        for (int ni = 0; ni < 4; ni++) {
            int r = m0 + wm + mi * 16 + g;
            int col = n0 + wn + ni * 8 + q * 2;
            size_t o0 = ((size_t)e * M + r) * N + col;
            size_t o1 = o0 + (size_t)8 * N;
            float v0 = acc[mi][ni][0], v1 = acc[mi][ni][1];
            float v2 = acc[mi][ni][2], v3 = acc[mi][ni][3];
            if (FUSE_GELU) {
                v0 = gelu_tanh_f(v0); v1 = gelu_tanh_f(v1);
                v2 = gelu_tanh_f(v2); v3 = gelu_tanh_f(v3);
                __half2 p0 = __floats2half2_rn(v0, v1);
                __half2 p1 = __floats2half2_rn(v2, v3);
                *(__half2*)(Ch + o0) = p0;
                *(__half2*)(Ch + o1) = p1;
            } else {
                *(float2*)(Cf + o0) = make_float2(v0, v1);
                *(float2*)(Cf + o1) = make_float2(v2, v3);
            }
        }
    }
}

// -------- host launch --------
extern "C" void kernel_launch(void* const* d_in, const int* in_sizes, int n_in,
                              void* d_out, int out_size) {
    const float* x = (const float*)d_in[0];
    const float* w1 = (const float*)d_in[1];
    const float* w2 = (const float*)d_in[2];
    float* out = (float*)d_out;

    __half *x16, *w1h, *w1l, *w2h, *w2l, *h16;
    cudaGetSymbolAddress((void**)&x16, g_x16);
    cudaGetSymbolAddress((void**)&w1h, g_w1h);
    cudaGetSymbolAddress((void**)&w1l, g_w1l);
    cudaGetSymbolAddress((void**)&w2h, g_w2h);
    cudaGetSymbolAddress((void**)&w2l, g_w2l);
    cudaGetSymbolAddress((void**)&h16, g_h16);

    cudaFuncSetAttribute(gemm_wm<true>, cudaFuncAttributeMaxDynamicSharedMemorySize, SMEM_TOTAL);
    cudaFuncSetAttribute(gemm_wm<false>, cudaFuncAttributeMaxDynamicSharedMemorySize, SMEM_TOTAL);

    // pre-pass
    size_t nx4 = (size_t)E_ * T_ * H_ / 4;
    conv16_k<<<(unsigned)((nx4 + 255) / 256), 256>>>(x, x16, nx4);
    tsplit16<<<dim3(F_ / 32, H_ / 32, E_), dim3(32, 8)>>>(w1, w1h, w1l, H_, F_);
    tsplit16<<<dim3(H_ / 32, F_ / 32, E_), dim3(32, 8)>>>(w2, w2h, w2l, F_, H_);

    // GEMM1 + GELU: A=x fp16 [T,H], B=w1^T fp16 hi/lo [F,H] -> h fp16 [T,F]
    gemm_wm<true><<<dim3(F_ / CTA_N, T_ / CTA_M, E_), NTHREADS, SMEM_TOTAL>>>(
        x16, w1h, w1l, nullptr, h16, T_, F_, H_);
    // GEMM2: A=h fp16 [T,F], B=w2^T fp16 hi/lo [H,F] -> out fp32 [T,H]
    gemm_wm<false><<<dim3(H_ / CTA_N, T_ / CTA_M, E_), NTHREADS, SMEM_TOTAL>>>(
        h16, w2h, w2l, out, nullptr, T_, H_, F_);
}